// round 13
// baseline (speedup 1.0000x reference)
#include <cuda_runtime.h>
#include <cuda_fp16.h>
#include <cuda_bf16.h>
#include <cstdint>

// ============================================================================
// Problem dimensions (fixed by the dataset)
// ============================================================================
static constexpr int M_DIM = 8192;
static constexpr int K_DIM = 4096;
static constexpr int N_DIM = 4096;
static constexpr int GROUPSZ = 16;

// Dequantized bf16 operands (exactly representable: e2m1 x e4m3 has <=6
// significand bits < bf16's 8). Static device scratch — no allocation.
__device__ __align__(256) __nv_bfloat16 g_A[(size_t)M_DIM * K_DIM];  // 64 MB
__device__ __align__(256) __nv_bfloat16 g_B[(size_t)N_DIM * K_DIM];  // 32 MB

// Manual e4m3fn round-to-nearest-even of a non-negative f32 (verified == HW
// cvt in R4/R9).
__device__ __forceinline__ float e4m3_rn_exact(float v) {
    if (v >= 0.015625f) {
        uint32_t u = __float_as_uint(v);
        uint32_t keep = u >> 20;                 // sign|exp|3 mantissa bits
        uint32_t drop = u & 0xFFFFFu;            // 20 discarded bits
        keep += (drop > 0x80000u) || (drop == 0x80000u && (keep & 1u));
        return __uint_as_float(keep << 20);      // carry propagates into exp
    } else {
        return rintf(v * 512.0f) * 0.001953125f; // RN-even on 2^-9 grid
    }
}

// ============================================================================
// Kernel 1: NVFP4 quantize-dequantize of x -> bf16 A [M,K]
// DIAGNOSTIC 4-WAY SPLIT by row m (error is row-separable):
//   m in [0,4096):    V1  v = t * RN(1/safe)            (rcp-mult division)
//   m in [4096,6144): V2  sc_in = amax * RN(inv/6)      (reassociated scale)
//   m in [6144,7168): V3  V1 and V2 combined
//   m in [7168,8192): baseline (R9 exact-IEEE path)
// ============================================================================
__global__ __launch_bounds__(256) void quant_x_kernel(
    const float* __restrict__ x, const float* __restrict__ input_scale) {
    int g = blockIdx.x * blockDim.x + threadIdx.x;   // one 16-elem group
    const int ngroups = M_DIM * K_DIM / GROUPSZ;
    if (g >= ngroups) return;

    int m = g >> 8;                                  // row = g / (K/16 = 256)
    bool useV1 = (m < 6144) && (m < 4096 || m >= 6144);  // rows [0,4096)
    bool useV2 = (m >= 4096 && m < 6144);
    if (m >= 6144 && m < 7168) { useV1 = true; useV2 = true; }  // V3 = both
    // m >= 7168: baseline (both false)

    float inv = __fdiv_rn(1.0f, input_scale[0]);     // input_scale_inv

    const float4* src = reinterpret_cast<const float4*>(x) + (size_t)g * 4;
    float f[16];
    float amax = 0.0f;
#pragma unroll
    for (int i = 0; i < 4; i++) {
        float4 v = src[i];
        f[4*i+0] = __half2float(__float2half(v.x));  // fp16 round-trip (RN)
        f[4*i+1] = __half2float(__float2half(v.y));
        f[4*i+2] = __half2float(__float2half(v.z));
        f[4*i+3] = __half2float(__float2half(v.w));
        amax = fmaxf(amax, fabsf(f[4*i+0]));
        amax = fmaxf(amax, fabsf(f[4*i+1]));
        amax = fmaxf(amax, fabsf(f[4*i+2]));
        amax = fmaxf(amax, fabsf(f[4*i+3]));
    }

    // Scale input: baseline RN(RN(amax/6)*inv); V2 reassociated amax*RN(inv/6)
    float sc_in;
    if (useV2) {
        sc_in = __fmul_rn(amax, __fdiv_rn(inv, 6.0f));
    } else {
        sc_in = __fmul_rn(__fdiv_rn(amax, 6.0f), inv);
    }
    float scale = e4m3_rn_exact(sc_in);
    float safe = (scale == 0.0f) ? 1.0f : scale;
    float rcp_safe = __frcp_rn(safe);                // RN(1/safe) for V1

    __nv_bfloat16 o[16];
#pragma unroll
    for (int i = 0; i < 16; i++) {
        float t = __fmul_rn(f[i], inv);
        float v = useV1 ? __fmul_rn(t, rcp_safe)     // V1: rcp-mult
                        : __fdiv_rn(t, safe);        // baseline: IEEE div
        float a = fminf(fabsf(v), 6.0f);
        // e2m1 round-to-nearest, ties at boundaries go UP (a >= bound in ref)
        float lvl;
        if      (a < 0.25f) lvl = 0.0f;
        else if (a < 0.75f) lvl = 0.5f;
        else if (a < 1.25f) lvl = 1.0f;
        else if (a < 1.75f) lvl = 1.5f;
        else if (a < 2.5f)  lvl = 2.0f;
        else if (a < 3.5f)  lvl = 3.0f;
        else if (a < 5.0f)  lvl = 4.0f;
        else                lvl = 6.0f;
        float q = (v < 0.0f) ? -lvl : lvl;
        o[i] = __float2bfloat16_rn(__fmul_rn(q, scale));  // exact in bf16
    }
    uint4* dst = reinterpret_cast<uint4*>(g_A + (size_t)g * GROUPSZ);
    dst[0] = *reinterpret_cast<uint4*>(o);
    dst[1] = *reinterpret_cast<uint4*>(o + 8);
}

// ============================================================================
// Kernel 2: decode packed fp4 weight nibbles * e4m3 scale -> bf16 B [N,K]
// (byte-identical to R9 — formally verified, no rounding decisions)
// ============================================================================
__global__ __launch_bounds__(256) void dequant_w_kernel(
    const int* __restrict__ w, const float* __restrict__ ws) {
    int t = blockIdx.x * blockDim.x + threadIdx.x;   // one 16-elem group
    const int gpr = K_DIM / GROUPSZ;                 // 256 groups per row
    const int total = N_DIM * gpr;
    if (t >= total) return;
    int n = t / gpr;
    int g = t - n * gpr;

    float scale = ws[t];   // ws is [N, K/16] row-major == t
    const int4* src = reinterpret_cast<const int4*>(
        w + (size_t)n * (K_DIM / 2) + (size_t)g * 8);
    int4 p0 = src[0], p1 = src[1];
    int pk[8] = {p0.x, p0.y, p0.z, p0.w, p1.x, p1.y, p1.z, p1.w};

    // e2m1 magnitudes {0,.5,1,1.5,2,3,4,6} *2 packed as nibbles: 0,1,2,3,4,6,8,12
    const uint32_t LUT2 = 0xC8643210u;

    __nv_bfloat16 o[16];
#pragma unroll
    for (int i = 0; i < 8; i++) {
        int b = pk[i] & 0xFF;
        int lo = b & 0xF, hi = (b >> 4) & 0xF;
        float vl = 0.5f * (float)((LUT2 >> ((lo & 7) * 4)) & 0xF);
        float vh = 0.5f * (float)((LUT2 >> ((hi & 7) * 4)) & 0xF);
        if (lo & 8) vl = -vl;
        if (hi & 8) vh = -vh;
        o[2*i]   = __float2bfloat16_rn(__fmul_rn(vl, scale));  // exact in bf16
        o[2*i+1] = __float2bfloat16_rn(__fmul_rn(vh, scale));
    }
    uint4* dst = reinterpret_cast<uint4*>(g_B + (size_t)n * K_DIM + (size_t)g * GROUPSZ);
    dst[0] = *reinterpret_cast<uint4*>(o);
    dst[1] = *reinterpret_cast<uint4*>(o + 8);
}

// ============================================================================
// Kernel 3: plain fp32 tiled SGEMM (validated in R12 — kept unchanged so the
// prepro split is the only variable this round).
//   out[M,N] = A[M,K] * B[N,K]^T * alpha + bias
// ============================================================================
__global__ __launch_bounds__(256)
void sgemm_kernel(float* __restrict__ out, const float* __restrict__ bias,
                  const float* __restrict__ isp, const float* __restrict__ ws2p) {
    __shared__ float As[16][128];
    __shared__ float Bs[16][128];

    int tid = threadIdx.x;
    int tx = tid & 15, ty = tid >> 4;          // 16x16 thread grid
    int bid = blockIdx.x;
    int tn0 = (bid & 31) * 128;                // 32 N tiles
    int tm0 = (bid >> 5) * 128;                // 64 M tiles

    float acc[8][8];
#pragma unroll
    for (int i = 0; i < 8; i++)
#pragma unroll
        for (int j = 0; j < 8; j++) acc[i][j] = 0.0f;

    int lrow = tid >> 1;                       // 0..127
    int lcol = (tid & 1) * 8;                  // 0 or 8
    const __nv_bfloat16* gA = g_A + (size_t)(tm0 + lrow) * K_DIM + lcol;
    const __nv_bfloat16* gB = g_B + (size_t)(tn0 + lrow) * K_DIM + lcol;

    for (int kt = 0; kt < K_DIM; kt += 16) {
        uint4 av = *reinterpret_cast<const uint4*>(gA + kt);
        uint4 bv = *reinterpret_cast<const uint4*>(gB + kt);
        const __nv_bfloat16* ah = reinterpret_cast<const __nv_bfloat16*>(&av);
        const __nv_bfloat16* bh = reinterpret_cast<const __nv_bfloat16*>(&bv);
#pragma unroll
        for (int j = 0; j < 8; j++) {
            As[lcol + j][lrow] = __bfloat162float(ah[j]);
            Bs[lcol + j][lrow] = __bfloat162float(bh[j]);
        }
        __syncthreads();

#pragma unroll
        for (int kk = 0; kk < 16; kk++) {
            float rA[8], rB[8];
#pragma unroll
            for (int i = 0; i < 8; i++) rA[i] = As[kk][ty * 8 + i];
#pragma unroll
            for (int j = 0; j < 8; j++) rB[j] = Bs[kk][tx * 8 + j];
#pragma unroll
            for (int i = 0; i < 8; i++)
#pragma unroll
                for (int j = 0; j < 8; j++)
                    acc[i][j] = fmaf(rA[i], rB[j], acc[i][j]);
        }
        __syncthreads();
    }

    float alpha = __fmul_rn(__ldg(isp), __ldg(ws2p));
#pragma unroll
    for (int i = 0; i < 8; i++) {
        int r = tm0 + ty * 8 + i;
        float* orow = out + (size_t)r * N_DIM;
#pragma unroll
        for (int j = 0; j < 8; j++) {
            int c = tn0 + tx * 8 + j;
            orow[c] = __fadd_rn(__fmul_rn(acc[i][j], alpha), __ldg(bias + c));
        }
    }
}

// ============================================================================
// Launch
// ============================================================================
extern "C" void kernel_launch(void* const* d_in, const int* in_sizes, int n_in,
                              void* d_out, int out_size) {
    const float* x       = (const float*)d_in[0];   // [M, K] f32
    const int*   w       = (const int*)d_in[1];     // [N, K/2] packed nibbles
    const float* wscale  = (const float*)d_in[2];   // [N, K/16] e4m3 values
    const float* iscale  = (const float*)d_in[3];   // scalar
    const float* wscale2 = (const float*)d_in[4];   // scalar
    const float* bias    = (const float*)d_in[5];   // [N]
    float* out = (float*)d_out;

    (void)in_sizes; (void)n_in; (void)out_size;

    int qgroups = M_DIM * K_DIM / GROUPSZ;   // 2,097,152
    int wgroups = N_DIM * K_DIM / GROUPSZ;   // 1,048,576
    quant_x_kernel<<<(qgroups + 255) / 256, 256>>>(x, iscale);
    dequant_w_kernel<<<(wgroups + 255) / 256, 256>>>(w, wscale);

    int tiles = (M_DIM / 128) * (N_DIM / 128);  // 2048
    sgemm_kernel<<<tiles, 256>>>(out, bias, iscale, wscale2);
}

// round 14
// speedup vs baseline: 8.2680x; 8.2680x over previous
#include <cuda_runtime.h>
#include <cuda_fp16.h>
#include <cuda_bf16.h>
#include <cstdint>

// ============================================================================
// Problem dimensions (fixed by the dataset)
// ============================================================================
static constexpr int M_DIM = 8192;
static constexpr int K_DIM = 4096;
static constexpr int N_DIM = 4096;
static constexpr int GROUPSZ = 16;

// Dequantized bf16 operands (exactly representable: e2m1 x e4m3 has <=6
// significand bits < bf16's 8). Static device scratch — no allocation.
__device__ __align__(256) __nv_bfloat16 g_A[(size_t)M_DIM * K_DIM];  // 64 MB
__device__ __align__(256) __nv_bfloat16 g_B[(size_t)N_DIM * K_DIM];  // 32 MB

// ============================================================================
// Helpers (sm_100 BASE target only — no tcgen05 / no 'a' features!)
// ============================================================================
__device__ __forceinline__ uint32_t smem_u32(const void* p) {
    uint32_t a;
    asm("{ .reg .u64 t; cvta.to.shared.u64 t, %1; cvt.u32.u64 %0, t; }"
        : "=r"(a) : "l"(p));
    return a;
}

#define SW128(o) ((uint32_t)(o) ^ ((((uint32_t)(o)) >> 3) & 0x70u))

__device__ __forceinline__ void ldsm_x4(uint32_t& r0, uint32_t& r1,
                                        uint32_t& r2, uint32_t& r3, uint32_t addr) {
    asm volatile("ldmatrix.sync.aligned.m8n8.x4.shared.b16 {%0,%1,%2,%3}, [%4];"
                 : "=r"(r0), "=r"(r1), "=r"(r2), "=r"(r3) : "r"(addr));
}

__device__ __forceinline__ void mma_16816(float* d, const uint32_t* a,
                                          uint32_t b0, uint32_t b1) {
    asm volatile(
        "mma.sync.aligned.m16n8k16.row.col.f32.bf16.bf16.f32 "
        "{%0,%1,%2,%3}, {%4,%5,%6,%7}, {%8,%9}, {%0,%1,%2,%3};"
        : "+f"(d[0]), "+f"(d[1]), "+f"(d[2]), "+f"(d[3])
        : "r"(a[0]), "r"(a[1]), "r"(a[2]), "r"(a[3]), "r"(b0), "r"(b1));
}

// Manual e4m3fn round-to-nearest-even of a non-negative f32 (verified == HW
// cvt in R4/R9; direct rounding, no f16 intermediate — R10 disproved that).
__device__ __forceinline__ float e4m3_rn_exact(float v) {
    if (v >= 0.015625f) {
        uint32_t u = __float_as_uint(v);
        uint32_t keep = u >> 20;                 // sign|exp|3 mantissa bits
        uint32_t drop = u & 0xFFFFFu;            // 20 discarded bits
        keep += (drop > 0x80000u) || (drop == 0x80000u && (keep & 1u));
        return __uint_as_float(keep << 20);      // carry propagates into exp
    } else {
        return rintf(v * 512.0f) * 0.001953125f; // RN-even on 2^-9 grid
    }
}

// ============================================================================
// Kernel 1: exact NVFP4 quantize-dequantize of x -> bf16 A [M,K]
// R13 region-decode verdict: the block division is lowered by XLA as
// multiply-by-RN-reciprocal (v = t * RN(1/safe)), measured error ~0.
// ============================================================================
__global__ __launch_bounds__(256) void quant_x_kernel(
    const float* __restrict__ x, const float* __restrict__ input_scale) {
    int g = blockIdx.x * blockDim.x + threadIdx.x;   // one 16-elem group
    const int ngroups = M_DIM * K_DIM / GROUPSZ;
    if (g >= ngroups) return;

    float inv = __fdiv_rn(1.0f, input_scale[0]);     // input_scale_inv

    const float4* src = reinterpret_cast<const float4*>(x) + (size_t)g * 4;
    float f[16];
    float amax = 0.0f;
#pragma unroll
    for (int i = 0; i < 4; i++) {
        float4 v = src[i];
        f[4*i+0] = __half2float(__float2half(v.x));  // fp16 round-trip (RN)
        f[4*i+1] = __half2float(__float2half(v.y));
        f[4*i+2] = __half2float(__float2half(v.z));
        f[4*i+3] = __half2float(__float2half(v.w));
        amax = fmaxf(amax, fabsf(f[4*i+0]));
        amax = fmaxf(amax, fabsf(f[4*i+1]));
        amax = fmaxf(amax, fabsf(f[4*i+2]));
        amax = fmaxf(amax, fabsf(f[4*i+3]));
    }

    // scale = e4m3_rn((amax / 6) * inv) — direct RN-even (validated)
    float sc_in = __fmul_rn(__fdiv_rn(amax, 6.0f), inv);
    float scale = e4m3_rn_exact(sc_in);
    float safe = (scale == 0.0f) ? 1.0f : scale;
    float rcp_safe = __frcp_rn(safe);                // XLA's rcp-mult division

    __nv_bfloat16 o[16];
#pragma unroll
    for (int i = 0; i < 16; i++) {
        float t = __fmul_rn(f[i], inv);
        float v = __fmul_rn(t, rcp_safe);            // V1 (validated R13)
        float a = fminf(fabsf(v), 6.0f);
        // e2m1 round-to-nearest, ties at boundaries go UP (a >= bound in ref)
        float lvl;
        if      (a < 0.25f) lvl = 0.0f;
        else if (a < 0.75f) lvl = 0.5f;
        else if (a < 1.25f) lvl = 1.0f;
        else if (a < 1.75f) lvl = 1.5f;
        else if (a < 2.5f)  lvl = 2.0f;
        else if (a < 3.5f)  lvl = 3.0f;
        else if (a < 5.0f)  lvl = 4.0f;
        else                lvl = 6.0f;
        float q = (v < 0.0f) ? -lvl : lvl;
        o[i] = __float2bfloat16_rn(__fmul_rn(q, scale));  // exact in bf16
    }
    uint4* dst = reinterpret_cast<uint4*>(g_A + (size_t)g * GROUPSZ);
    dst[0] = *reinterpret_cast<uint4*>(o);
    dst[1] = *reinterpret_cast<uint4*>(o + 8);
}

// ============================================================================
// Kernel 2: decode packed fp4 weight nibbles * e4m3 scale -> bf16 B [N,K]
// ============================================================================
__global__ __launch_bounds__(256) void dequant_w_kernel(
    const int* __restrict__ w, const float* __restrict__ ws) {
    int t = blockIdx.x * blockDim.x + threadIdx.x;   // one 16-elem group
    const int gpr = K_DIM / GROUPSZ;                 // 256 groups per row
    const int total = N_DIM * gpr;
    if (t >= total) return;
    int n = t / gpr;
    int g = t - n * gpr;

    float scale = ws[t];   // ws is [N, K/16] row-major == t
    const int4* src = reinterpret_cast<const int4*>(
        w + (size_t)n * (K_DIM / 2) + (size_t)g * 8);
    int4 p0 = src[0], p1 = src[1];
    int pk[8] = {p0.x, p0.y, p0.z, p0.w, p1.x, p1.y, p1.z, p1.w};

    // e2m1 magnitudes {0,.5,1,1.5,2,3,4,6} *2 packed as nibbles: 0,1,2,3,4,6,8,12
    const uint32_t LUT2 = 0xC8643210u;

    __nv_bfloat16 o[16];
#pragma unroll
    for (int i = 0; i < 8; i++) {
        int b = pk[i] & 0xFF;
        int lo = b & 0xF, hi = (b >> 4) & 0xF;
        float vl = 0.5f * (float)((LUT2 >> ((lo & 7) * 4)) & 0xF);
        float vh = 0.5f * (float)((LUT2 >> ((hi & 7) * 4)) & 0xF);
        if (lo & 8) vl = -vl;
        if (hi & 8) vh = -vh;
        o[2*i]   = __float2bfloat16_rn(__fmul_rn(vl, scale));  // exact in bf16
        o[2*i+1] = __float2bfloat16_rn(__fmul_rn(vh, scale));
    }
    uint4* dst = reinterpret_cast<uint4*>(g_B + (size_t)n * K_DIM + (size_t)g * GROUPSZ);
    dst[0] = *reinterpret_cast<uint4*>(o);
    dst[1] = *reinterpret_cast<uint4*>(o + 8);
}

// ============================================================================
// Kernel 3: mma.sync (HMMA) bf16 GEMM  out[M,N] = A[M,K]*B[N,K]^T*alpha + bias
// CTA 128x256, K-chunk 64, 8 warps (2x4), each warp 64x64, 3-stage cp.async.
// (Validated: produced bit-identical output to the plain SGEMM in R9/R12.)
// ============================================================================
static constexpr int BM = 128;
static constexpr int BN = 256;
static constexpr int KCH = 64;                         // K elems per chunk (128B rows)
static constexpr int STAGES = 3;
static constexpr int A_BYTES = BM * 128;               // 16 KB
static constexpr int B_BYTES = BN * 128;               // 32 KB
static constexpr int STAGE_BYTES = A_BYTES + B_BYTES;  // 48 KB
static constexpr int SMEM_DYN = STAGES * STAGE_BYTES + 1024;

__device__ __forceinline__ void prefetch_chunk(
    uint32_t sA, uint32_t sB,
    const __nv_bfloat16* gA_tile, const __nv_bfloat16* gB_tile, int tid) {
    // A tile: 128 rows x 128B = 1024 x 16B segments; 8 segs per row
#pragma unroll
    for (int i = 0; i < 4; i++) {
        int seg = tid + i * 256;
        const char* src = reinterpret_cast<const char*>(
            gA_tile + (size_t)(seg >> 3) * K_DIM) + (seg & 7) * 16;
        asm volatile("cp.async.cg.shared.global [%0], [%1], 16;"
                     :: "r"(sA + SW128(seg * 16)), "l"(src));
    }
    // B tile: 256 rows x 128B = 2048 segments
#pragma unroll
    for (int i = 0; i < 8; i++) {
        int seg = tid + i * 256;
        const char* src = reinterpret_cast<const char*>(
            gB_tile + (size_t)(seg >> 3) * K_DIM) + (seg & 7) * 16;
        asm volatile("cp.async.cg.shared.global [%0], [%1], 16;"
                     :: "r"(sB + SW128(seg * 16)), "l"(src));
    }
}

__global__ __launch_bounds__(256, 1)
void fp4gemm_kernel(float* __restrict__ out, const float* __restrict__ bias,
                    const float* __restrict__ isp, const float* __restrict__ ws2p) {
    extern __shared__ char dynsmem[];
    uint32_t dyn_base = (smem_u32(dynsmem) + 1023u) & ~1023u;  // SW128 atom align
    int tid = threadIdx.x;
    int wid = tid >> 5, lane = tid & 31;

    // n-fastest raster: consecutive CTAs share an A strip; B (32MB) stays in L2.
    const int TILES_N = N_DIM / BN;  // 16
    int tn0 = (blockIdx.x % TILES_N) * BN;
    int tm0 = (blockIdx.x / TILES_N) * BM;

    // Warp layout: 2 (M) x 4 (N), each warp owns a 64x64 output tile.
    int wm = (wid & 1) * 64;
    int wn = (wid >> 1) * 64;

    // ldmatrix lane->address decomposition (4 groups of 8 lanes)
    int lr = lane & 7, grp = lane >> 3;
    // A x4 matrices: (m+0,k0),(m+8,k0),(m+0,k8),(m+8,k8)
    int a_row = ((grp & 1) ? 8 : 0) + lr;
    int a_s16 = (grp >> 1);
    // B x4 matrices: (n+0,k0),(n+0,k8),(n+8,k0),(n+8,k8)  -> r0,r1 / r2,r3 frags
    int b_row = ((grp >> 1) ? 8 : 0) + lr;
    int b_s16 = (grp & 1);

    const __nv_bfloat16* gA0 = g_A + (size_t)tm0 * K_DIM;
    const __nv_bfloat16* gB0 = g_B + (size_t)tn0 * K_DIM;

    float acc[4][8][4];
#pragma unroll
    for (int i = 0; i < 4; i++)
#pragma unroll
        for (int j = 0; j < 8; j++)
#pragma unroll
            for (int c = 0; c < 4; c++) acc[i][j][c] = 0.0f;

    // Prologue: prefetch chunks 0 and 1
#pragma unroll
    for (int i = 0; i < STAGES - 1; i++) {
        uint32_t sb = dyn_base + i * STAGE_BYTES;
        prefetch_chunk(sb, sb + A_BYTES, gA0 + i * KCH, gB0 + i * KCH, tid);
        asm volatile("cp.async.commit_group;" ::: "memory");
    }

    const int NCH = K_DIM / KCH;  // 64
    for (int i = 0; i < NCH; i++) {
        int s = i - (i / STAGES) * STAGES;
        uint32_t sA = dyn_base + s * STAGE_BYTES;
        uint32_t sB = sA + A_BYTES;

        if (i < NCH - 1) {
            asm volatile("cp.async.wait_group %0;" :: "n"(STAGES - 2) : "memory");
        } else {
            asm volatile("cp.async.wait_group 0;" ::: "memory");
        }
        __syncthreads();

        // Prefetch chunk i+2 into the slot freed by chunk i-1
        if (i + STAGES - 1 < NCH) {
            int sp = (i + STAGES - 1) % STAGES;
            uint32_t pb = dyn_base + sp * STAGE_BYTES;
            prefetch_chunk(pb, pb + A_BYTES,
                           gA0 + (size_t)(i + STAGES - 1) * KCH,
                           gB0 + (size_t)(i + STAGES - 1) * KCH, tid);
            asm volatile("cp.async.commit_group;" ::: "memory");
        }

        // Compute: 4 k-steps of 16
#pragma unroll
        for (int ks = 0; ks < 4; ks++) {
            uint32_t afr[4][4];
#pragma unroll
            for (int mi = 0; mi < 4; mi++) {
                uint32_t addr = sA + SW128((uint32_t)((wm + mi * 16 + a_row) * 128
                                                      + ks * 32 + a_s16 * 16));
                ldsm_x4(afr[mi][0], afr[mi][1], afr[mi][2], afr[mi][3], addr);
            }
            uint32_t bfr[4][4];
#pragma unroll
            for (int jp = 0; jp < 4; jp++) {
                uint32_t addr = sB + SW128((uint32_t)((wn + jp * 16 + b_row) * 128
                                                      + ks * 32 + b_s16 * 16));
                ldsm_x4(bfr[jp][0], bfr[jp][1], bfr[jp][2], bfr[jp][3], addr);
            }
#pragma unroll
            for (int mi = 0; mi < 4; mi++) {
#pragma unroll
                for (int jp = 0; jp < 4; jp++) {
                    mma_16816(acc[mi][2*jp],     afr[mi], bfr[jp][0], bfr[jp][1]);
                    mma_16816(acc[mi][2*jp + 1], afr[mi], bfr[jp][2], bfr[jp][3]);
                }
            }
        }
    }

    // ------------------------------------------------------------------------
    // Epilogue: (acc * alpha) + bias with the reference's exact two roundings
    // (c-frag: row = lane/4 (+8), col = (lane%4)*2)
    // ------------------------------------------------------------------------
    float alpha = __fmul_rn(__ldg(isp), __ldg(ws2p));
    int gq = lane >> 2, qt = lane & 3;

    float2 bv[8];
#pragma unroll
    for (int nj = 0; nj < 8; nj++) {
        int c0 = tn0 + wn + nj * 8 + qt * 2;
        bv[nj] = make_float2(__ldg(bias + c0), __ldg(bias + c0 + 1));
    }

#pragma unroll
    for (int mi = 0; mi < 4; mi++) {
#pragma unroll
        for (int h = 0; h < 2; h++) {
            int row = tm0 + wm + mi * 16 + gq + h * 8;
            float* orow = out + (size_t)row * N_DIM;
#pragma unroll
            for (int nj = 0; nj < 8; nj++) {
                int c0 = tn0 + wn + nj * 8 + qt * 2;
                float2 v;
                v.x = __fadd_rn(__fmul_rn(acc[mi][nj][h * 2],     alpha), bv[nj].x);
                v.y = __fadd_rn(__fmul_rn(acc[mi][nj][h * 2 + 1], alpha), bv[nj].y);
                *reinterpret_cast<float2*>(orow + c0) = v;
            }
        }
    }
}

// ============================================================================
// Launch
// ============================================================================
extern "C" void kernel_launch(void* const* d_in, const int* in_sizes, int n_in,
                              void* d_out, int out_size) {
    const float* x       = (const float*)d_in[0];   // [M, K] f32
    const int*   w       = (const int*)d_in[1];     // [N, K/2] packed nibbles
    const float* wscale  = (const float*)d_in[2];   // [N, K/16] e4m3 values
    const float* iscale  = (const float*)d_in[3];   // scalar
    const float* wscale2 = (const float*)d_in[4];   // scalar
    const float* bias    = (const float*)d_in[5];   // [N]
    float* out = (float*)d_out;

    (void)in_sizes; (void)n_in; (void)out_size;

    cudaFuncSetAttribute(fp4gemm_kernel,
                         cudaFuncAttributeMaxDynamicSharedMemorySize, SMEM_DYN);

    int qgroups = M_DIM * K_DIM / GROUPSZ;   // 2,097,152
    int wgroups = N_DIM * K_DIM / GROUPSZ;   // 1,048,576
    quant_x_kernel<<<(qgroups + 255) / 256, 256>>>(x, iscale);
    dequant_w_kernel<<<(wgroups + 255) / 256, 256>>>(w, wscale);

    int tiles = (M_DIM / BM) * (N_DIM / BN);  // 1024
    fp4gemm_kernel<<<tiles, 256, SMEM_DYN>>>(out, bias, iscale, wscale2);
}

// round 15
// speedup vs baseline: 8.4242x; 1.0189x over previous
#include <cuda_runtime.h>
#include <cuda_fp16.h>
#include <cuda_bf16.h>
#include <cstdint>

// ============================================================================
// Problem dimensions (fixed by the dataset)
// ============================================================================
static constexpr int M_DIM = 8192;
static constexpr int K_DIM = 4096;
static constexpr int N_DIM = 4096;
static constexpr int GROUPSZ = 16;

// Dequantized bf16 operands (exactly representable: e2m1 x e4m3 has <=6
// significand bits < bf16's 8). Static device scratch — no allocation.
__device__ __align__(256) __nv_bfloat16 g_A[(size_t)M_DIM * K_DIM];  // 64 MB
__device__ __align__(256) __nv_bfloat16 g_B[(size_t)N_DIM * K_DIM];  // 32 MB

// ============================================================================
// Helpers (sm_100 BASE target only — no tcgen05 / no 'a' features!)
// ============================================================================
__device__ __forceinline__ uint32_t smem_u32(const void* p) {
    uint32_t a;
    asm("{ .reg .u64 t; cvta.to.shared.u64 t, %1; cvt.u32.u64 %0, t; }"
        : "=r"(a) : "l"(p));
    return a;
}

#define SW128(o) ((uint32_t)(o) ^ ((((uint32_t)(o)) >> 3) & 0x70u))

__device__ __forceinline__ void ldsm_x4(uint32_t& r0, uint32_t& r1,
                                        uint32_t& r2, uint32_t& r3, uint32_t addr) {
    asm volatile("ldmatrix.sync.aligned.m8n8.x4.shared.b16 {%0,%1,%2,%3}, [%4];"
                 : "=r"(r0), "=r"(r1), "=r"(r2), "=r"(r3) : "r"(addr));
}

__device__ __forceinline__ void mma_16816(float* d, const uint32_t* a,
                                          uint32_t b0, uint32_t b1) {
    asm volatile(
        "mma.sync.aligned.m16n8k16.row.col.f32.bf16.bf16.f32 "
        "{%0,%1,%2,%3}, {%4,%5,%6,%7}, {%8,%9}, {%0,%1,%2,%3};"
        : "+f"(d[0]), "+f"(d[1]), "+f"(d[2]), "+f"(d[3])
        : "r"(a[0]), "r"(a[1]), "r"(a[2]), "r"(a[3]), "r"(b0), "r"(b1));
}

// Manual e4m3fn round-to-nearest-even of a non-negative f32 (verified == HW
// cvt; direct rounding, no f16 intermediate).
__device__ __forceinline__ float e4m3_rn_exact(float v) {
    if (v >= 0.015625f) {
        uint32_t u = __float_as_uint(v);
        uint32_t keep = u >> 20;                 // sign|exp|3 mantissa bits
        uint32_t drop = u & 0xFFFFFu;            // 20 discarded bits
        keep += (drop > 0x80000u) || (drop == 0x80000u && (keep & 1u));
        return __uint_as_float(keep << 20);      // carry propagates into exp
    } else {
        return rintf(v * 512.0f) * 0.001953125f; // RN-even on 2^-9 grid
    }
}

// ============================================================================
// Kernel 1 (MERGED prepro): one launch, blockIdx dispatch.
//   blocks [0, 8192):      quant_x   (g = b*256+tid, 16-elem group)
//   blocks [8192, 12288):  dequant_w (t = (b-8192)*256+tid)
// Numerics of both paths byte-identical to the R14 bit-exact kernels.
// ============================================================================
static constexpr int QUANT_BLOCKS = (M_DIM * K_DIM / GROUPSZ) / 256;  // 8192
static constexpr int DEQ_BLOCKS   = (N_DIM * K_DIM / GROUPSZ) / 256;  // 4096

__global__ __launch_bounds__(256) void prepro_kernel(
    const float* __restrict__ x, const float* __restrict__ input_scale,
    const int* __restrict__ w, const float* __restrict__ ws) {
    int b = blockIdx.x;
    if (b < QUANT_BLOCKS) {
        // ---- quant_x path ----
        int g = b * 256 + threadIdx.x;               // one 16-elem group

        float inv = __fdiv_rn(1.0f, input_scale[0]); // input_scale_inv

        const float4* src = reinterpret_cast<const float4*>(x) + (size_t)g * 4;
        float f[16];
        float amax = 0.0f;
#pragma unroll
        for (int i = 0; i < 4; i++) {
            float4 v = src[i];
            f[4*i+0] = __half2float(__float2half(v.x));  // fp16 round-trip (RN)
            f[4*i+1] = __half2float(__float2half(v.y));
            f[4*i+2] = __half2float(__float2half(v.z));
            f[4*i+3] = __half2float(__float2half(v.w));
            amax = fmaxf(amax, fabsf(f[4*i+0]));
            amax = fmaxf(amax, fabsf(f[4*i+1]));
            amax = fmaxf(amax, fabsf(f[4*i+2]));
            amax = fmaxf(amax, fabsf(f[4*i+3]));
        }

        // scale = e4m3_rn((amax / 6) * inv) — direct RN-even (validated)
        float sc_in = __fmul_rn(__fdiv_rn(amax, 6.0f), inv);
        float scale = e4m3_rn_exact(sc_in);
        float safe = (scale == 0.0f) ? 1.0f : scale;
        float rcp_safe = __frcp_rn(safe);            // XLA's rcp-mult division

        __nv_bfloat16 o[16];
#pragma unroll
        for (int i = 0; i < 16; i++) {
            float t = __fmul_rn(f[i], inv);
            float v = __fmul_rn(t, rcp_safe);        // validated R13
            float a = fminf(fabsf(v), 6.0f);
            float lvl;
            if      (a < 0.25f) lvl = 0.0f;
            else if (a < 0.75f) lvl = 0.5f;
            else if (a < 1.25f) lvl = 1.0f;
            else if (a < 1.75f) lvl = 1.5f;
            else if (a < 2.5f)  lvl = 2.0f;
            else if (a < 3.5f)  lvl = 3.0f;
            else if (a < 5.0f)  lvl = 4.0f;
            else                lvl = 6.0f;
            float q = (v < 0.0f) ? -lvl : lvl;
            o[i] = __float2bfloat16_rn(__fmul_rn(q, scale));  // exact in bf16
        }
        uint4* dst = reinterpret_cast<uint4*>(g_A + (size_t)g * GROUPSZ);
        dst[0] = *reinterpret_cast<uint4*>(o);
        dst[1] = *reinterpret_cast<uint4*>(o + 8);
    } else {
        // ---- dequant_w path ----
        int t = (b - QUANT_BLOCKS) * 256 + threadIdx.x;  // one 16-elem group
        const int gpr = K_DIM / GROUPSZ;                 // 256 groups per row
        int n = t / gpr;
        int g = t - n * gpr;

        float scale = ws[t];   // ws is [N, K/16] row-major == t
        const int4* src = reinterpret_cast<const int4*>(
            w + (size_t)n * (K_DIM / 2) + (size_t)g * 8);
        int4 p0 = src[0], p1 = src[1];
        int pk[8] = {p0.x, p0.y, p0.z, p0.w, p1.x, p1.y, p1.z, p1.w};

        // e2m1 magnitudes {0,.5,1,1.5,2,3,4,6}*2 as nibbles: 0,1,2,3,4,6,8,12
        const uint32_t LUT2 = 0xC8643210u;

        __nv_bfloat16 o[16];
#pragma unroll
        for (int i = 0; i < 8; i++) {
            int by = pk[i] & 0xFF;
            int lo = by & 0xF, hi = (by >> 4) & 0xF;
            float vl = 0.5f * (float)((LUT2 >> ((lo & 7) * 4)) & 0xF);
            float vh = 0.5f * (float)((LUT2 >> ((hi & 7) * 4)) & 0xF);
            if (lo & 8) vl = -vl;
            if (hi & 8) vh = -vh;
            o[2*i]   = __float2bfloat16_rn(__fmul_rn(vl, scale));
            o[2*i+1] = __float2bfloat16_rn(__fmul_rn(vh, scale));
        }
        uint4* dst = reinterpret_cast<uint4*>(
            g_B + (size_t)n * K_DIM + (size_t)g * GROUPSZ);
        dst[0] = *reinterpret_cast<uint4*>(o);
        dst[1] = *reinterpret_cast<uint4*>(o + 8);
    }
}

// ============================================================================
// Kernel 2: mma.sync (HMMA) bf16 GEMM  out[M,N] = A[M,K]*B[N,K]^T*alpha + bias
// CTA 128x256, K-chunk 64, 8 warps (2x4), each warp 64x64.
// 4-stage cp.async pipeline + DOUBLE-BUFFERED register fragments so LDSM
// latency overlaps the previous k-step's MMAs. MMA accumulation order is
// unchanged from the bit-exact R14 kernel.
// ============================================================================
static constexpr int BM = 128;
static constexpr int BN = 256;
static constexpr int KCH = 64;                         // K elems per chunk (128B rows)
static constexpr int STAGES = 4;
static constexpr int A_BYTES = BM * 128;               // 16 KB
static constexpr int B_BYTES = BN * 128;               // 32 KB
static constexpr int STAGE_BYTES = A_BYTES + B_BYTES;  // 48 KB
static constexpr int SMEM_DYN = STAGES * STAGE_BYTES + 1024;  // ~193 KB

__device__ __forceinline__ void prefetch_chunk(
    uint32_t sA, uint32_t sB,
    const __nv_bfloat16* gA_tile, const __nv_bfloat16* gB_tile, int tid) {
    // A tile: 128 rows x 128B = 1024 x 16B segments; 8 segs per row
#pragma unroll
    for (int i = 0; i < 4; i++) {
        int seg = tid + i * 256;
        const char* src = reinterpret_cast<const char*>(
            gA_tile + (size_t)(seg >> 3) * K_DIM) + (seg & 7) * 16;
        asm volatile("cp.async.cg.shared.global [%0], [%1], 16;"
                     :: "r"(sA + SW128(seg * 16)), "l"(src));
    }
    // B tile: 256 rows x 128B = 2048 segments
#pragma unroll
    for (int i = 0; i < 8; i++) {
        int seg = tid + i * 256;
        const char* src = reinterpret_cast<const char*>(
            gB_tile + (size_t)(seg >> 3) * K_DIM) + (seg & 7) * 16;
        asm volatile("cp.async.cg.shared.global [%0], [%1], 16;"
                     :: "r"(sB + SW128(seg * 16)), "l"(src));
    }
}

__global__ __launch_bounds__(256, 1)
void fp4gemm_kernel(float* __restrict__ out, const float* __restrict__ bias,
                    const float* __restrict__ isp, const float* __restrict__ ws2p) {
    extern __shared__ char dynsmem[];
    uint32_t dyn_base = (smem_u32(dynsmem) + 1023u) & ~1023u;  // SW128 atom align
    int tid = threadIdx.x;
    int wid = tid >> 5, lane = tid & 31;

    // n-fastest raster: consecutive CTAs share an A strip; B (32MB) stays in L2.
    const int TILES_N = N_DIM / BN;  // 16
    int tn0 = (blockIdx.x % TILES_N) * BN;
    int tm0 = (blockIdx.x / TILES_N) * BM;

    // Warp layout: 2 (M) x 4 (N), each warp owns a 64x64 output tile.
    int wm = (wid & 1) * 64;
    int wn = (wid >> 1) * 64;

    // ldmatrix lane->address decomposition (4 groups of 8 lanes)
    int lr = lane & 7, grp = lane >> 3;
    int a_row = ((grp & 1) ? 8 : 0) + lr;
    int a_s16 = (grp >> 1);
    int b_row = ((grp >> 1) ? 8 : 0) + lr;
    int b_s16 = (grp & 1);

    const __nv_bfloat16* gA0 = g_A + (size_t)tm0 * K_DIM;
    const __nv_bfloat16* gB0 = g_B + (size_t)tn0 * K_DIM;

    float acc[4][8][4];
#pragma unroll
    for (int i = 0; i < 4; i++)
#pragma unroll
        for (int j = 0; j < 8; j++)
#pragma unroll
            for (int c = 0; c < 4; c++) acc[i][j][c] = 0.0f;

    // Prologue: prefetch chunks 0..STAGES-2
#pragma unroll
    for (int i = 0; i < STAGES - 1; i++) {
        uint32_t sb = dyn_base + i * STAGE_BYTES;
        prefetch_chunk(sb, sb + A_BYTES, gA0 + i * KCH, gB0 + i * KCH, tid);
        asm volatile("cp.async.commit_group;" ::: "memory");
    }

    const int NCH = K_DIM / KCH;  // 64
#pragma unroll 1
    for (int i = 0; i < NCH; i++) {
        int s = i & (STAGES - 1);
        uint32_t sA = dyn_base + s * STAGE_BYTES;
        uint32_t sB = sA + A_BYTES;

        if (i < NCH - 1) {
            asm volatile("cp.async.wait_group %0;" :: "n"(STAGES - 2) : "memory");
        } else {
            asm volatile("cp.async.wait_group 0;" ::: "memory");
        }
        __syncthreads();

        // Prefetch chunk i+STAGES-1 into the stage freed by chunk i-1
        if (i + STAGES - 1 < NCH) {
            int sp = (i + STAGES - 1) & (STAGES - 1);
            uint32_t pb = dyn_base + sp * STAGE_BYTES;
            prefetch_chunk(pb, pb + A_BYTES,
                           gA0 + (size_t)(i + STAGES - 1) * KCH,
                           gB0 + (size_t)(i + STAGES - 1) * KCH, tid);
            asm volatile("cp.async.commit_group;" ::: "memory");
        }

        // Double-buffered fragments: load ks+1 while computing ks.
        uint32_t afr[2][4][4], bfr[2][4][4];

        // load k-step 0 into buffer 0
#pragma unroll
        for (int mi = 0; mi < 4; mi++) {
            uint32_t addr = sA + SW128((uint32_t)((wm + mi * 16 + a_row) * 128
                                                  + a_s16 * 16));
            ldsm_x4(afr[0][mi][0], afr[0][mi][1], afr[0][mi][2], afr[0][mi][3], addr);
        }
#pragma unroll
        for (int jp = 0; jp < 4; jp++) {
            uint32_t addr = sB + SW128((uint32_t)((wn + jp * 16 + b_row) * 128
                                                  + b_s16 * 16));
            ldsm_x4(bfr[0][jp][0], bfr[0][jp][1], bfr[0][jp][2], bfr[0][jp][3], addr);
        }

#pragma unroll
        for (int ks = 0; ks < 4; ks++) {
            int cur = ks & 1, nxt = cur ^ 1;
            if (ks < 3) {
#pragma unroll
                for (int mi = 0; mi < 4; mi++) {
                    uint32_t addr = sA + SW128((uint32_t)(
                        (wm + mi * 16 + a_row) * 128 + (ks + 1) * 32 + a_s16 * 16));
                    ldsm_x4(afr[nxt][mi][0], afr[nxt][mi][1],
                            afr[nxt][mi][2], afr[nxt][mi][3], addr);
                }
#pragma unroll
                for (int jp = 0; jp < 4; jp++) {
                    uint32_t addr = sB + SW128((uint32_t)(
                        (wn + jp * 16 + b_row) * 128 + (ks + 1) * 32 + b_s16 * 16));
                    ldsm_x4(bfr[nxt][jp][0], bfr[nxt][jp][1],
                            bfr[nxt][jp][2], bfr[nxt][jp][3], addr);
                }
            }
#pragma unroll
            for (int mi = 0; mi < 4; mi++) {
#pragma unroll
                for (int jp = 0; jp < 4; jp++) {
                    mma_16816(acc[mi][2*jp],     afr[cur][mi],
                              bfr[cur][jp][0], bfr[cur][jp][1]);
                    mma_16816(acc[mi][2*jp + 1], afr[cur][mi],
                              bfr[cur][jp][2], bfr[cur][jp][3]);
                }
            }
        }
    }

    // ------------------------------------------------------------------------
    // Epilogue: (acc * alpha) + bias with the reference's exact two roundings
    // ------------------------------------------------------------------------
    float alpha = __fmul_rn(__ldg(isp), __ldg(ws2p));
    int gq = lane >> 2, qt = lane & 3;

    float2 bv[8];
#pragma unroll
    for (int nj = 0; nj < 8; nj++) {
        int c0 = tn0 + wn + nj * 8 + qt * 2;
        bv[nj] = make_float2(__ldg(bias + c0), __ldg(bias + c0 + 1));
    }

#pragma unroll
    for (int mi = 0; mi < 4; mi++) {
#pragma unroll
        for (int h = 0; h < 2; h++) {
            int row = tm0 + wm + mi * 16 + gq + h * 8;
            float* orow = out + (size_t)row * N_DIM;
#pragma unroll
            for (int nj = 0; nj < 8; nj++) {
                int c0 = tn0 + wn + nj * 8 + qt * 2;
                float2 v;
                v.x = __fadd_rn(__fmul_rn(acc[mi][nj][h * 2],     alpha), bv[nj].x);
                v.y = __fadd_rn(__fmul_rn(acc[mi][nj][h * 2 + 1], alpha), bv[nj].y);
                *reinterpret_cast<float2*>(orow + c0) = v;
            }
        }
    }
}

// ============================================================================
// Launch
// ============================================================================
extern "C" void kernel_launch(void* const* d_in, const int* in_sizes, int n_in,
                              void* d_out, int out_size) {
    const float* x       = (const float*)d_in[0];   // [M, K] f32
    const int*   w       = (const int*)d_in[1];     // [N, K/2] packed nibbles
    const float* wscale  = (const float*)d_in[2];   // [N, K/16] e4m3 values
    const float* iscale  = (const float*)d_in[3];   // scalar
    const float* wscale2 = (const float*)d_in[4];   // scalar
    const float* bias    = (const float*)d_in[5];   // [N]
    float* out = (float*)d_out;

    (void)in_sizes; (void)n_in; (void)out_size;

    cudaFuncSetAttribute(fp4gemm_kernel,
                         cudaFuncAttributeMaxDynamicSharedMemorySize, SMEM_DYN);

    prepro_kernel<<<QUANT_BLOCKS + DEQ_BLOCKS, 256>>>(x, iscale, w, wscale);

    int tiles = (M_DIM / BM) * (N_DIM / BN);  // 1024
    fp4gemm_kernel<<<tiles, 256, SMEM_DYN>>>(out, bias, iscale, wscale2);
}